// round 13
// baseline (speedup 1.0000x reference)
#include <cuda_runtime.h>
#include <cuda_fp16.h>
#include <cstdint>
#include <math.h>

// ---------------- problem constants ----------------
#define T_TOK 4096
#define DD    1024
#define HH    2048
#define EE    8
#define CAP   4096
#define NEXP  9          // 8 routed + shared as "expert 8"

// ---------------- tile config: 256x128 CTA, 8 warps of 64x64 ----------------
#define BM 256
#define BN 128
#define BK 64            // k halfs per chunk (128B rows -> SW128)
#define NSTAGE 3
#define S_B   32768      // B plane offset inside a stage (A: 256 rows x 128B)
#define STG   49152      // stage bytes: A 32KB + B 16KB
#define SMEM_DYN (NSTAGE * STG)   // 147456

typedef unsigned int u32;
typedef unsigned long long u64;

// ---------------- device scratch ----------------
__device__ int   g_cnt[EE];
__device__ int   g_tok[EE * CAP];
__device__ float g_wt [EE * CAP];
__device__ __half g_xh [(size_t)T_TOK * DD];
__device__ __half g_wgu[(size_t)NEXP * 4096 * DD];   // interleaved gate/up rows
__device__ __half g_wd [(size_t)NEXP * DD * HH];
__device__ __half g_hh [(size_t)NEXP * CAP * HH];

// ---------------- helpers ----------------
__device__ __forceinline__ u32 smem_u32(const void* p) {
    u32 a; asm("{ .reg .u64 t; cvta.to.shared.u64 t, %1; cvt.u32.u64 %0, t; }" : "=r"(a) : "l"(p));
    return a;
}
__device__ __forceinline__ void cpa16(u32 dst, const void* gsrc) {
    asm volatile("cp.async.cg.shared.global [%0], [%1], 16;" :: "r"(dst), "l"(gsrc) : "memory");
}
#define CP_COMMIT() asm volatile("cp.async.commit_group;" ::: "memory")
#define CP_WAIT(n)  asm volatile("cp.async.wait_group %0;" :: "n"(n) : "memory")

__device__ __forceinline__ void ldsm4(u32* r, u32 addr) {
    asm volatile("ldmatrix.sync.aligned.m8n8.x4.shared.b16 {%0,%1,%2,%3}, [%4];"
        : "=r"(r[0]), "=r"(r[1]), "=r"(r[2]), "=r"(r[3]) : "r"(addr));
}
__device__ __forceinline__ void mma16816(float* c, const u32* a, u32 b0, u32 b1) {
    asm volatile("mma.sync.aligned.m16n8k16.row.col.f32.f16.f16.f32 "
        "{%0,%1,%2,%3}, {%4,%5,%6,%7}, {%8,%9}, {%0,%1,%2,%3};"
        : "+f"(c[0]), "+f"(c[1]), "+f"(c[2]), "+f"(c[3])
        : "r"(a[0]), "r"(a[1]), "r"(a[2]), "r"(a[3]), "r"(b0), "r"(b1));
}
__device__ __forceinline__ uint2 pack_hi(float4 v) {
    __half2 h0 = __floats2half2_rn(v.x, v.y);
    __half2 h1 = __floats2half2_rn(v.z, v.w);
    uint2 r; r.x = *(u32*)&h0; r.y = *(u32*)&h1; return r;
}

// ---------------- kernel: zero output ----------------
__global__ void zero_kernel(float4* out4, int n4) {
    int i = blockIdx.x * blockDim.x + threadIdx.x;
    if (i < n4) out4[i] = make_float4(0.f, 0.f, 0.f, 0.f);
}

// ---------------- conversion kernels ----------------
__global__ void conv_x_kernel(const float* __restrict__ x) {
    int t = blockIdx.x, c = threadIdx.x;               // 256 thr = DD/4
    if (blockIdx.x == 0 && threadIdx.x < EE) g_cnt[threadIdx.x] = 0;
    float4 v = ((const float4*)(x + (size_t)t * DD))[c];
    ((uint2*)g_xh)[(size_t)t * 256 + c] = pack_hi(v);
}
__global__ void conv_wgu_kernel(const float* __restrict__ Wg, const float* __restrict__ Wu,
                                const float* __restrict__ sg, const float* __restrict__ su) {
    int b = blockIdx.x;                                 // row in [0, NEXP*4096)
    int e = b >> 12, r = b & 4095;
    const float* src;
    if (e < EE) src = ((r & 1) ? Wu : Wg) + ((size_t)e * HH + (size_t)(r >> 1)) * DD;
    else        src = ((r & 1) ? su : sg) + (size_t)(r >> 1) * DD;
    float4 v = ((const float4*)src)[threadIdx.x];
    ((uint2*)g_wgu)[(size_t)b * 256 + threadIdx.x] = pack_hi(v);
}
__global__ void conv_wd_kernel(const float* __restrict__ Wd, const float* __restrict__ sd) {
    int b = blockIdx.x;                                 // row in [0, NEXP*DD), 512 thr
    int e = b >> 10, d = b & 1023;
    const float* src = (e < EE) ? Wd + ((size_t)e * DD + (size_t)d) * HH
                                : sd + (size_t)d * HH;
    float4 v = ((const float4*)src)[threadIdx.x];
    ((uint2*)g_wd)[(size_t)b * 512 + threadIdx.x] = pack_hi(v);
}

// ---------------- router ----------------
__global__ void router_kernel(const float* __restrict__ x,
                              const float* __restrict__ wr) {
    int t = blockIdx.x, w = threadIdx.x >> 5, lane = threadIdx.x & 31;
    const float* xr = x + (size_t)t * DD;
    const float* wrow = wr + (size_t)w * DD;
    float s = 0.f;
    for (int d = lane; d < DD; d += 32) s += xr[d] * wrow[d];
    #pragma unroll
    for (int o = 16; o; o >>= 1) s += __shfl_xor_sync(0xffffffffu, s, o);
    __shared__ float lg[EE];
    if (lane == 0) lg[w] = s;
    __syncthreads();
    if (threadIdx.x == 0) {
        int i0 = 0; float m0 = lg[0];
        #pragma unroll
        for (int j = 1; j < EE; ++j) if (lg[j] > m0) { m0 = lg[j]; i0 = j; }
        int i1 = -1; float m1 = -INFINITY;
        #pragma unroll
        for (int j = 0; j < EE; ++j) if (j != i0 && lg[j] > m1) { m1 = lg[j]; i1 = j; }
        float w0 = 1.f / (1.f + expf(m1 - m0));
        float w1 = 1.f - w0;
        int p0 = atomicAdd(&g_cnt[i0], 1);
        g_tok[i0 * CAP + p0] = t; g_wt[i0 * CAP + p0] = w0;
        int p1 = atomicAdd(&g_cnt[i1], 1);
        g_tok[i1 * CAP + p1] = t; g_wt[i1 * CAP + p1] = w1;
    }
}

// ---------------- consumer machinery (8 warps, 4x2 grid, warp tile 64x64) ----------------
#define FRAG_SETUP() \
    int wm = wid & 3, wn = wid >> 2; \
    int ks0 = wn << 1; \
    int lr = lane & 15, lkb = lane >> 4; \
    u32 fsw = (u32)((lr & 7) << 4); \
    u32 baseA[4], baseB[4]; \
    _Pragma("unroll") \
    for (int mb = 0; mb < 4; ++mb) \
        baseA[mb] = (u32)((wm * 64 + mb * 16 + lr) * 128 + lkb * 16); \
    _Pragma("unroll") \
    for (int nb = 0; nb < 4; ++nb) \
        baseB[nb] = (u32)(S_B + (wn * 64 + nb * 16 + lr) * 128 + lkb * 16); \
    float acc[4][8][4]; \
    _Pragma("unroll") \
    for (int a_ = 0; a_ < 4; ++a_) \
        _Pragma("unroll") \
        for (int b_ = 0; b_ < 8; ++b_) \
            _Pragma("unroll") \
            for (int c_ = 0; c_ < 4; ++c_) acc[a_][b_][c_] = 0.f;

#define CONSUME(cur) \
    _Pragma("unroll") \
    for (int i_ = 0; i_ < 4; ++i_) { \
        int ks = (ks0 + i_) & 3; \
        u32 af[4][4], bf[4][4]; \
        _Pragma("unroll") \
        for (int mb = 0; mb < 4; ++mb) \
            ldsm4(af[mb], (cur) + ((baseA[mb] + ks * 32) ^ fsw)); \
        _Pragma("unroll") \
        for (int nb = 0; nb < 4; ++nb) \
            ldsm4(bf[nb], (cur) + ((baseB[nb] + ks * 32) ^ fsw)); \
        _Pragma("unroll") \
        for (int mb = 0; mb < 4; ++mb) \
            _Pragma("unroll") \
            for (int nb = 0; nb < 4; ++nb) { \
                mma16816(acc[mb][nb * 2],     af[mb], bf[nb][0], bf[nb][2]); \
                mma16816(acc[mb][nb * 2 + 1], af[mb], bf[nb][1], bf[nb][3]); \
            } \
    }

// R7/R12 mainloop (proven): CP_WAIT before barrier, ISSUE after barrier.
#define MAINLOOP(NC) \
    ISSUE(0); CP_COMMIT(); \
    ISSUE(1); CP_COMMIT(); \
    for (int kt = 0; kt < (NC); ++kt) { \
        CP_WAIT(1); \
        __syncthreads(); \
        if (kt + 2 < (NC)) ISSUE(kt + 2); \
        CP_COMMIT(); \
        u32 cur = sb + (u32)(kt % NSTAGE) * STG; \
        CONSUME(cur); \
    }

// =====================================================================
// GEMM1: C[256,128] = Xg[256,1024] . Wgu^T ; epilogue SwiGLU -> g_hh
// =====================================================================
__global__ void __launch_bounds__(256, 1)
gemm1_kernel() {
    int e = blockIdx.z;
    int ne = (e == EE) ? T_TOK : g_cnt[e];
    int mbase = blockIdx.y * BM;
    if (mbase >= ne) return;
    int ntile = blockIdx.x;

    extern __shared__ char smem[];
    u32 sb = smem_u32(smem);
    __shared__ int s_tok[256];
    int tid = threadIdx.x, wid = tid >> 5, lane = tid & 31;
    {
        int r = mbase + tid;
        s_tok[tid] = (e == EE) ? r : ((r < ne) ? g_tok[e * CAP + r] : g_tok[e * CAP]);
    }
    __syncthreads();

    // ---- coalesced producer setup ----
    // A: 256 rows -> 8 ops/thread: row = pw*32 + j*4 + psub; pc sweeps 128B chunk.
    // B: 128 rows -> 4 ops/thread: row = pw*16 + j*4 + psub.
    int pw = tid >> 5, psub = (tid >> 3) & 3, pc = tid & 7;
    u32 sOffA[8], aOff[8], sOffB[4];
    #pragma unroll
    for (int j = 0; j < 8; ++j) {
        int r = pw * 32 + j * 4 + psub;
        sOffA[j] = ((u32)(r * 128 + pc * 16)) ^ ((u32)((r & 7) << 4));
        aOff[j] = (u32)s_tok[r] * DD + (u32)(pc * 8);
    }
    #pragma unroll
    for (int j = 0; j < 4; ++j) {
        int r = pw * 16 + j * 4 + psub;
        sOffB[j] = ((u32)(r * 128 + pc * 16)) ^ ((u32)((r & 7) << 4));
    }
    const __half* bSrc = g_wgu + (size_t)(e * 4096 + ntile * BN + pw * 16 + psub) * DD + pc * 8;

#define ISSUE(s) do { \
    u32 _st = sb + (u32)((s) % NSTAGE) * STG; \
    _Pragma("unroll") \
    for (int j = 0; j < 8; ++j) cpa16(_st + sOffA[j], g_xh + aOff[j] + (s) * BK); \
    _Pragma("unroll") \
    for (int j = 0; j < 4; ++j) cpa16(_st + S_B + sOffB[j], bSrc + j * 4 * DD + (s) * BK); \
} while (0)

    FRAG_SETUP();
    MAINLOOP(DD / BK);   // 16 chunks
#undef ISSUE

    // epilogue: SwiGLU -> fp16 h (R8 mapping, warp tile 64x64)
    size_t slotBase = (size_t)e * CAP + mbase;
    int rq = lane >> 2, cq = lane & 3;
    #pragma unroll
    for (int mb = 0; mb < 4; ++mb)
        #pragma unroll
        for (int nt = 0; nt < 8; ++nt) {
            int hcol = ntile * 64 + wn * 32 + nt * 4 + cq;
            float* c = acc[mb][nt];
            #pragma unroll
            for (int half = 0; half < 2; ++half) {
                int r = wm * 64 + mb * 16 + rq + half * 8;
                float gv = c[half * 2], uv = c[half * 2 + 1];
                float hv = (gv / (1.f + __expf(-gv))) * uv;
                g_hh[(slotBase + (size_t)r) * HH + (size_t)hcol] = __float2half_rn(hv);
            }
        }
}

// =====================================================================
// GEMM2: C[256,128] = h[256,2048] . Wd^T ; split-K=2; atomic scatter
// =====================================================================
__global__ void __launch_bounds__(256, 1)
gemm2_kernel(float* __restrict__ out) {
    int z = blockIdx.z;
    int e = z >> 1, kh = z & 1;
    int ne = (e == EE) ? T_TOK : g_cnt[e];
    int mbase = blockIdx.y * BM;
    if (mbase >= ne) return;
    int ntile = blockIdx.x;

    extern __shared__ char smem[];
    u32 sb = smem_u32(smem);
    __shared__ int   s_tok[256];
    __shared__ float s_wt[256];
    int tid = threadIdx.x, wid = tid >> 5, lane = tid & 31;
    {
        int r = mbase + tid;
        if (e == EE)     { s_tok[tid] = r; s_wt[tid] = 1.f; }
        else if (r < ne) { s_tok[tid] = g_tok[e * CAP + r]; s_wt[tid] = g_wt[e * CAP + r]; }
        else             { s_tok[tid] = 0; s_wt[tid] = 0.f; }
    }
    __syncthreads();

    size_t slotBase = (size_t)e * CAP + mbase;
    size_t koff = (size_t)kh * (HH / 2);

    // ---- coalesced producer setup (both sources contiguous rows) ----
    int pw = tid >> 5, psub = (tid >> 3) & 3, pc = tid & 7;
    u32 sOffA[8], sOffB[4];
    #pragma unroll
    for (int j = 0; j < 8; ++j) {
        int r = pw * 32 + j * 4 + psub;
        sOffA[j] = ((u32)(r * 128 + pc * 16)) ^ ((u32)((r & 7) << 4));
    }
    #pragma unroll
    for (int j = 0; j < 4; ++j) {
        int r = pw * 16 + j * 4 + psub;
        sOffB[j] = ((u32)(r * 128 + pc * 16)) ^ ((u32)((r & 7) << 4));
    }
    const __half* aSrc = g_hh + (slotBase + (size_t)(pw * 32 + psub)) * HH + koff + pc * 8;
    const __half* bSrc = g_wd + (size_t)(e * DD + ntile * BN + pw * 16 + psub) * HH + koff + pc * 8;

#define ISSUE(s) do { \
    u32 _st = sb + (u32)((s) % NSTAGE) * STG; \
    _Pragma("unroll") \
    for (int j = 0; j < 8; ++j) cpa16(_st + sOffA[j], aSrc + j * 4 * HH + (s) * BK); \
    _Pragma("unroll") \
    for (int j = 0; j < 4; ++j) cpa16(_st + S_B + sOffB[j], bSrc + j * 4 * HH + (s) * BK); \
} while (0)

    FRAG_SETUP();
    MAINLOOP((HH / 2) / BK);  // 16 chunks per split half
#undef ISSUE

    // epilogue: weighted atomic scatter (R8 mapping)
    int nv = ne - mbase; if (nv > BM) nv = BM;
    int rq = lane >> 2, cq = lane & 3;
    #pragma unroll
    for (int mb = 0; mb < 4; ++mb)
        #pragma unroll
        for (int nt = 0; nt < 8; ++nt) {
            int col = ntile * BN + wn * 64 + nt * 8 + cq * 2;
            float* c = acc[mb][nt];
            #pragma unroll
            for (int half = 0; half < 2; ++half) {
                int r = wm * 64 + mb * 16 + rq + half * 8;
                if (r < nv) {
                    int tok = s_tok[r]; float wt = s_wt[r];
                    float* orow = out + (size_t)tok * DD + col;
                    atomicAdd(orow,     wt * c[half * 2]);
                    atomicAdd(orow + 1, wt * c[half * 2 + 1]);
                }
            }
        }
}

// ---------------- launch ----------------
extern "C" void kernel_launch(void* const* d_in, const int* in_sizes, int n_in,
                              void* d_out, int out_size) {
    const float* x  = (const float*)d_in[0];
    const float* wr = (const float*)d_in[1];
    const float* Wg = (const float*)d_in[2];
    const float* Wu = (const float*)d_in[3];
    const float* Wd = (const float*)d_in[4];
    const float* sg = (const float*)d_in[5];
    const float* su = (const float*)d_in[6];
    const float* sd = (const float*)d_in[7];
    float* out = (float*)d_out;

    cudaFuncSetAttribute(gemm1_kernel, cudaFuncAttributeMaxDynamicSharedMemorySize, SMEM_DYN);
    cudaFuncSetAttribute(gemm2_kernel, cudaFuncAttributeMaxDynamicSharedMemorySize, SMEM_DYN);

    // order chosen so gemm1 is launch #4 (the slot ncu profiles)
    conv_x_kernel<<<T_TOK, 256>>>(x);                 // also inits g_cnt
    router_kernel<<<T_TOK, 256>>>(x, wr);
    conv_wgu_kernel<<<NEXP * 4096, 256>>>(Wg, Wu, sg, su);

    dim3 g1(32, 16, NEXP);       // N-tiles(4096/128), M-tiles(4096/256), experts
    gemm1_kernel<<<g1, 256, SMEM_DYN>>>();

    int n4 = out_size / 4;
    zero_kernel<<<(n4 + 255) / 256, 256>>>((float4*)out, n4);
    conv_wd_kernel<<<NEXP * DD, 512>>>(Wd, sd);

    dim3 g2(8, 16, NEXP * 2);    // N-tiles(1024/128), M-tiles(4096/256), experts x split-K
    gemm2_kernel<<<g2, 256, SMEM_DYN>>>(out);
}

// round 14
// speedup vs baseline: 1.2221x; 1.2221x over previous
#include <cuda_runtime.h>
#include <cuda_fp16.h>
#include <cstdint>
#include <math.h>

// ---------------- problem constants ----------------
#define T_TOK 4096
#define DD    1024
#define HH    2048
#define EE    8
#define CAP   4096
#define NEXP  9          // 8 routed + shared as "expert 8"

// ---------------- tile config (R12, proven best) ----------------
#define BM 128
#define BN 128
#define BK 64            // k halfs per chunk (128B rows -> SW128)
#define NSTAGE 3
#define S_B   16384      // B plane offset inside a stage
#define STG   32768      // stage bytes: A 16KB + B 16KB
#define SMEM_DYN (NSTAGE * STG)   // 98304

typedef unsigned int u32;
typedef unsigned long long u64;

// ---------------- device scratch ----------------
__device__ int   g_cnt[EE];
__device__ int   g_tok[EE * CAP];
__device__ float g_wt [EE * CAP];
__device__ __half g_xh [(size_t)T_TOK * DD];
__device__ __half g_wgu[(size_t)NEXP * 4096 * DD];   // interleaved gate/up rows
__device__ __half g_wd [(size_t)NEXP * DD * HH];
__device__ __half g_hh [(size_t)NEXP * CAP * HH];

// ---------------- helpers ----------------
__device__ __forceinline__ u32 smem_u32(const void* p) {
    u32 a; asm("{ .reg .u64 t; cvta.to.shared.u64 t, %1; cvt.u32.u64 %0, t; }" : "=r"(a) : "l"(p));
    return a;
}
__device__ __forceinline__ void cpa16(u32 dst, const void* gsrc) {
    asm volatile("cp.async.cg.shared.global [%0], [%1], 16;" :: "r"(dst), "l"(gsrc) : "memory");
}
#define CP_COMMIT() asm volatile("cp.async.commit_group;" ::: "memory")
#define CP_WAIT(n)  asm volatile("cp.async.wait_group %0;" :: "n"(n) : "memory")

__device__ __forceinline__ void ldsm4(u32* r, u32 addr) {
    asm volatile("ldmatrix.sync.aligned.m8n8.x4.shared.b16 {%0,%1,%2,%3}, [%4];"
        : "=r"(r[0]), "=r"(r[1]), "=r"(r[2]), "=r"(r[3]) : "r"(addr));
}
__device__ __forceinline__ void mma16816(float* c, const u32* a, u32 b0, u32 b1) {
    asm volatile("mma.sync.aligned.m16n8k16.row.col.f32.f16.f16.f32 "
        "{%0,%1,%2,%3}, {%4,%5,%6,%7}, {%8,%9}, {%0,%1,%2,%3};"
        : "+f"(c[0]), "+f"(c[1]), "+f"(c[2]), "+f"(c[3])
        : "r"(a[0]), "r"(a[1]), "r"(a[2]), "r"(a[3]), "r"(b0), "r"(b1));
}
__device__ __forceinline__ uint2 pack_hi(float4 v) {
    __half2 h0 = __floats2half2_rn(v.x, v.y);
    __half2 h1 = __floats2half2_rn(v.z, v.w);
    uint2 r; r.x = *(u32*)&h0; r.y = *(u32*)&h1; return r;
}

// ---------------- kernel: zero output ----------------
__global__ void zero_kernel(float4* out4, int n4) {
    int i = blockIdx.x * blockDim.x + threadIdx.x;
    if (i < n4) out4[i] = make_float4(0.f, 0.f, 0.f, 0.f);
}

// ---------------- fused conv_x + router (x read once, hot in L1/L2) ----------------
__global__ void conv_x_router_kernel(const float* __restrict__ x,
                                     const float* __restrict__ wr) {
    int t = blockIdx.x;
    int tid = threadIdx.x, w = tid >> 5, lane = tid & 31;
    if (blockIdx.x == 0 && tid < EE) g_cnt[tid] = 0;

    // convert this token's row to fp16
    float4 v = ((const float4*)(x + (size_t)t * DD))[tid];
    ((uint2*)g_xh)[(size_t)t * 256 + tid] = pack_hi(v);

    // router: warp w computes logit for expert w
    const float* xr = x + (size_t)t * DD;
    const float* wrow = wr + (size_t)w * DD;
    float s = 0.f;
    for (int d = lane; d < DD; d += 32) s += xr[d] * wrow[d];
    #pragma unroll
    for (int o = 16; o; o >>= 1) s += __shfl_xor_sync(0xffffffffu, s, o);
    __shared__ float lg[EE];
    if (lane == 0) lg[w] = s;
    __syncthreads();
    if (tid == 0) {
        int i0 = 0; float m0 = lg[0];
        #pragma unroll
        for (int j = 1; j < EE; ++j) if (lg[j] > m0) { m0 = lg[j]; i0 = j; }
        int i1 = -1; float m1 = -INFINITY;
        #pragma unroll
        for (int j = 0; j < EE; ++j) if (j != i0 && lg[j] > m1) { m1 = lg[j]; i1 = j; }
        float w0 = 1.f / (1.f + expf(m1 - m0));
        float w1 = 1.f - w0;
        int p0 = atomicAdd(&g_cnt[i0], 1);
        g_tok[i0 * CAP + p0] = t; g_wt[i0 * CAP + p0] = w0;
        int p1 = atomicAdd(&g_cnt[i1], 1);
        g_tok[i1 * CAP + p1] = t; g_wt[i1 * CAP + p1] = w1;
    }
}

// ---------------- weight conversion kernels ----------------
__global__ void conv_wgu_kernel(const float* __restrict__ Wg, const float* __restrict__ Wu,
                                const float* __restrict__ sg, const float* __restrict__ su) {
    int b = blockIdx.x;                                 // row in [0, NEXP*4096)
    int e = b >> 12, r = b & 4095;
    const float* src;
    if (e < EE) src = ((r & 1) ? Wu : Wg) + ((size_t)e * HH + (size_t)(r >> 1)) * DD;
    else        src = ((r & 1) ? su : sg) + (size_t)(r >> 1) * DD;
    float4 v = ((const float4*)src)[threadIdx.x];
    ((uint2*)g_wgu)[(size_t)b * 256 + threadIdx.x] = pack_hi(v);
}
__global__ void conv_wd_kernel(const float* __restrict__ Wd, const float* __restrict__ sd) {
    int b = blockIdx.x;                                 // row in [0, NEXP*DD), 512 thr
    int e = b >> 10, d = b & 1023;
    const float* src = (e < EE) ? Wd + ((size_t)e * DD + (size_t)d) * HH
                                : sd + (size_t)d * HH;
    float4 v = ((const float4*)src)[threadIdx.x];
    ((uint2*)g_wd)[(size_t)b * 512 + threadIdx.x] = pack_hi(v);
}

// ---------------- consumer machinery (R12 verbatim) ----------------
#define FRAG_SETUP() \
    int wm = wid & 3, wn = wid >> 2; \
    int ks0 = (wid >> 2) << 1; \
    int lr = lane & 15, lkb = lane >> 4; \
    u32 fsw = (u32)((lr & 7) << 4); \
    u32 baseA[2], baseB[4]; \
    _Pragma("unroll") \
    for (int tm = 0; tm < 2; ++tm) \
        baseA[tm] = (u32)((wm * 32 + tm * 16 + lr) * 128 + lkb * 16); \
    _Pragma("unroll") \
    for (int nb = 0; nb < 4; ++nb) \
        baseB[nb] = (u32)(S_B + (wn * 64 + nb * 16 + lr) * 128 + lkb * 16); \
    float acc[2][8][4]; \
    _Pragma("unroll") \
    for (int a_ = 0; a_ < 2; ++a_) \
        _Pragma("unroll") \
        for (int b_ = 0; b_ < 8; ++b_) \
            _Pragma("unroll") \
            for (int c_ = 0; c_ < 4; ++c_) acc[a_][b_][c_] = 0.f;

#define CONSUME(cur) \
    _Pragma("unroll") \
    for (int i_ = 0; i_ < 4; ++i_) { \
        int ks = (ks0 + i_) & 3; \
        u32 af[2][4], bf[4][4]; \
        _Pragma("unroll") \
        for (int tm = 0; tm < 2; ++tm) \
            ldsm4(af[tm], (cur) + ((baseA[tm] + ks * 32) ^ fsw)); \
        _Pragma("unroll") \
        for (int nb = 0; nb < 4; ++nb) \
            ldsm4(bf[nb], (cur) + ((baseB[nb] + ks * 32) ^ fsw)); \
        _Pragma("unroll") \
        for (int mt = 0; mt < 2; ++mt) \
            _Pragma("unroll") \
            for (int nb = 0; nb < 4; ++nb) { \
                mma16816(acc[mt][nb * 2],     af[mt], bf[nb][0], bf[nb][2]); \
                mma16816(acc[mt][nb * 2 + 1], af[mt], bf[nb][1], bf[nb][3]); \
            } \
    }

// R7/R12 mainloop (proven): CP_WAIT before barrier, ISSUE after barrier.
#define MAINLOOP(NC) \
    ISSUE(0); CP_COMMIT(); \
    ISSUE(1); CP_COMMIT(); \
    for (int kt = 0; kt < (NC); ++kt) { \
        CP_WAIT(1); \
        __syncthreads(); \
        if (kt + 2 < (NC)) ISSUE(kt + 2); \
        CP_COMMIT(); \
        u32 cur = sb + (u32)(kt % NSTAGE) * STG; \
        CONSUME(cur); \
    }

// =====================================================================
// GEMM1: C[128,128] = Xg[128,1024] . Wgu^T ; epilogue SwiGLU -> g_hh
// =====================================================================
__global__ void __launch_bounds__(256, 2)
gemm1_kernel() {
    int e = blockIdx.z;
    int ne = (e == EE) ? T_TOK : g_cnt[e];
    int mbase = blockIdx.y * BM;
    if (mbase >= ne) return;
    int ntile = blockIdx.x;

    extern __shared__ char smem[];
    u32 sb = smem_u32(smem);
    __shared__ int s_tok[128];
    int tid = threadIdx.x, wid = tid >> 5, lane = tid & 31;
    if (tid < 128) {
        int r = mbase + tid;
        s_tok[tid] = (e == EE) ? r : ((r < ne) ? g_tok[e * CAP + r] : g_tok[e * CAP]);
    }
    __syncthreads();

    // ---- coalesced producer setup (R12) ----
    int pw = tid >> 5, psub = (tid >> 3) & 3, pc = tid & 7;
    u32 sOff[4];
    const __half* aSrc[4];
    #pragma unroll
    for (int j = 0; j < 4; ++j) {
        int r = pw * 16 + j * 4 + psub;
        sOff[j] = ((u32)(r * 128 + pc * 16)) ^ ((u32)((r & 7) << 4));
        aSrc[j] = g_xh + (size_t)s_tok[r] * DD + pc * 8;
    }
    const __half* bSrc = g_wgu + (size_t)(e * 4096 + ntile * BN + pw * 16 + psub) * DD + pc * 8;

#define ISSUE(s) do { \
    u32 _st = sb + (u32)((s) % NSTAGE) * STG; \
    _Pragma("unroll") \
    for (int j = 0; j < 4; ++j) cpa16(_st + sOff[j], aSrc[j] + (s) * BK); \
    _Pragma("unroll") \
    for (int j = 0; j < 4; ++j) cpa16(_st + S_B + sOff[j], bSrc + j * 4 * DD + (s) * BK); \
} while (0)

    FRAG_SETUP();
    MAINLOOP(DD / BK);   // 16 chunks
#undef ISSUE

    // epilogue: SwiGLU -> fp16 h
    size_t slotBase = (size_t)e * CAP + mbase;
    int rbase = wm * 32 + (lane >> 2), cquad = lane & 3;
    #pragma unroll
    for (int mt = 0; mt < 2; ++mt)
        #pragma unroll
        for (int nt = 0; nt < 8; ++nt) {
            int hcol = ntile * 64 + wn * 32 + nt * 4 + cquad;
            float* c = acc[mt][nt];
            #pragma unroll
            for (int half = 0; half < 2; ++half) {
                int r = rbase + mt * 16 + half * 8;
                float gv = c[half * 2], uv = c[half * 2 + 1];
                float h = (gv / (1.f + __expf(-gv))) * uv;
                g_hh[(slotBase + (size_t)r) * HH + (size_t)hcol] = __float2half_rn(h);
            }
        }
}

// =====================================================================
// GEMM2: C[128,128] = h[128,2048] . Wd^T ; full K per CTA; atomic scatter
// =====================================================================
__global__ void __launch_bounds__(256, 2)
gemm2_kernel(float* __restrict__ out) {
    int e = blockIdx.z;
    int ne = (e == EE) ? T_TOK : g_cnt[e];
    int mbase = blockIdx.y * BM;
    if (mbase >= ne) return;
    int ntile = blockIdx.x;

    extern __shared__ char smem[];
    u32 sb = smem_u32(smem);
    __shared__ int   s_tok[128];
    __shared__ float s_wt[128];
    int tid = threadIdx.x, wid = tid >> 5, lane = tid & 31;
    if (tid < 128) {
        int r = mbase + tid;
        if (e == EE)     { s_tok[tid] = r; s_wt[tid] = 1.f; }
        else if (r < ne) { s_tok[tid] = g_tok[e * CAP + r]; s_wt[tid] = g_wt[e * CAP + r]; }
        else             { s_tok[tid] = 0; s_wt[tid] = 0.f; }
    }
    __syncthreads();

    size_t slotBase = (size_t)e * CAP + mbase;

    // ---- coalesced producer setup (both sources contiguous rows) ----
    int pw = tid >> 5, psub = (tid >> 3) & 3, pc = tid & 7;
    u32 sOff[4];
    #pragma unroll
    for (int j = 0; j < 4; ++j) {
        int r = pw * 16 + j * 4 + psub;
        sOff[j] = ((u32)(r * 128 + pc * 16)) ^ ((u32)((r & 7) << 4));
    }
    const __half* aSrc = g_hh + (slotBase + (size_t)(pw * 16 + psub)) * HH + pc * 8;
    const __half* bSrc = g_wd + (size_t)(e * DD + ntile * BN + pw * 16 + psub) * HH + pc * 8;

#define ISSUE(s) do { \
    u32 _st = sb + (u32)((s) % NSTAGE) * STG; \
    _Pragma("unroll") \
    for (int j = 0; j < 4; ++j) cpa16(_st + sOff[j], aSrc + j * 4 * HH + (s) * BK); \
    _Pragma("unroll") \
    for (int j = 0; j < 4; ++j) cpa16(_st + S_B + sOff[j], bSrc + j * 4 * HH + (s) * BK); \
} while (0)

    FRAG_SETUP();
    MAINLOOP(HH / BK);  // 32 chunks, full K
#undef ISSUE

    // epilogue: weighted atomic scatter
    int nv = ne - mbase; if (nv > BM) nv = BM;
    int rbase = wm * 32 + (lane >> 2), cquad = lane & 3;
    #pragma unroll
    for (int mt = 0; mt < 2; ++mt)
        #pragma unroll
        for (int nt = 0; nt < 8; ++nt) {
            int col = ntile * BN + wn * 64 + nt * 8 + cquad * 2;
            float* c = acc[mt][nt];
            #pragma unroll
            for (int half = 0; half < 2; ++half) {
                int r = rbase + mt * 16 + half * 8;
                if (r < nv) {
                    int tok = s_tok[r]; float wt = s_wt[r];
                    float* orow = out + (size_t)tok * DD + col;
                    atomicAdd(orow,     wt * c[half * 2]);
                    atomicAdd(orow + 1, wt * c[half * 2 + 1]);
                }
            }
        }
}

// ---------------- launch ----------------
extern "C" void kernel_launch(void* const* d_in, const int* in_sizes, int n_in,
                              void* d_out, int out_size) {
    const float* x  = (const float*)d_in[0];
    const float* wr = (const float*)d_in[1];
    const float* Wg = (const float*)d_in[2];
    const float* Wu = (const float*)d_in[3];
    const float* Wd = (const float*)d_in[4];
    const float* sg = (const float*)d_in[5];
    const float* su = (const float*)d_in[6];
    const float* sd = (const float*)d_in[7];
    float* out = (float*)d_out;

    cudaFuncSetAttribute(gemm1_kernel, cudaFuncAttributeMaxDynamicSharedMemorySize, SMEM_DYN);
    cudaFuncSetAttribute(gemm2_kernel, cudaFuncAttributeMaxDynamicSharedMemorySize, SMEM_DYN);

    // order keeps gemm1 as launch #4 (the slot ncu profiles)
    conv_x_router_kernel<<<T_TOK, 256>>>(x, wr);      // fused; also inits g_cnt
    conv_wgu_kernel<<<NEXP * 4096, 256>>>(Wg, Wu, sg, su);
    conv_wd_kernel<<<NEXP * DD, 512>>>(Wd, sd);

    dim3 g1(32, 32, NEXP);       // N-tiles(4096/128), M-tiles(4096/128), experts
    gemm1_kernel<<<g1, 256, SMEM_DYN>>>();

    int n4 = out_size / 4;
    zero_kernel<<<(n4 + 255) / 256, 256>>>((float4*)out, n4);

    dim3 g2(8, 32, NEXP);        // N-tiles(1024/128), M-tiles, experts (no split-K)
    gemm2_kernel<<<g2, 256, SMEM_DYN>>>(out);
}

// round 15
// speedup vs baseline: 1.2323x; 1.0084x over previous
#include <cuda_runtime.h>
#include <cuda_fp16.h>
#include <cstdint>
#include <math.h>

// ---------------- problem constants ----------------
#define T_TOK 4096
#define DD    1024
#define HH    2048
#define EE    8
#define CAP   4096
#define NEXP  9          // 8 routed + shared as "expert 8"

// ---------------- tile config (R12/R14, proven best) ----------------
#define BM 128
#define BN 128
#define BK 64            // k halfs per chunk (128B rows -> SW128)
#define NSTAGE 3
#define S_B   16384      // B plane offset inside a stage
#define STG   32768      // stage bytes: A 16KB + B 16KB
#define SMEM_DYN (NSTAGE * STG)   // 98304

typedef unsigned int u32;
typedef unsigned long long u64;

// ---------------- device scratch ----------------
__device__ int   g_cnt[EE];
__device__ int   g_tok[EE * CAP];
__device__ float g_wt [EE * CAP];
__device__ __half g_xh [(size_t)T_TOK * DD];
__device__ __half g_wgu[(size_t)NEXP * 4096 * DD];   // interleaved gate/up rows
__device__ __half g_wd [(size_t)NEXP * DD * HH];
__device__ __half g_hh [(size_t)NEXP * CAP * HH];

// ---------------- helpers ----------------
__device__ __forceinline__ u32 smem_u32(const void* p) {
    u32 a; asm("{ .reg .u64 t; cvta.to.shared.u64 t, %1; cvt.u32.u64 %0, t; }" : "=r"(a) : "l"(p));
    return a;
}
__device__ __forceinline__ void cpa16(u32 dst, const void* gsrc) {
    asm volatile("cp.async.cg.shared.global [%0], [%1], 16;" :: "r"(dst), "l"(gsrc) : "memory");
}
#define CP_COMMIT() asm volatile("cp.async.commit_group;" ::: "memory")
#define CP_WAIT(n)  asm volatile("cp.async.wait_group %0;" :: "n"(n) : "memory")

__device__ __forceinline__ void ldsm4(u32* r, u32 addr) {
    asm volatile("ldmatrix.sync.aligned.m8n8.x4.shared.b16 {%0,%1,%2,%3}, [%4];"
        : "=r"(r[0]), "=r"(r[1]), "=r"(r[2]), "=r"(r[3]) : "r"(addr));
}
__device__ __forceinline__ void mma16816(float* c, const u32* a, u32 b0, u32 b1) {
    asm volatile("mma.sync.aligned.m16n8k16.row.col.f32.f16.f16.f32 "
        "{%0,%1,%2,%3}, {%4,%5,%6,%7}, {%8,%9}, {%0,%1,%2,%3};"
        : "+f"(c[0]), "+f"(c[1]), "+f"(c[2]), "+f"(c[3])
        : "r"(a[0]), "r"(a[1]), "r"(a[2]), "r"(a[3]), "r"(b0), "r"(b1));
}
__device__ __forceinline__ uint2 pack_hi(float4 v) {
    __half2 h0 = __floats2half2_rn(v.x, v.y);
    __half2 h1 = __floats2half2_rn(v.z, v.w);
    uint2 r; r.x = *(u32*)&h0; r.y = *(u32*)&h1; return r;
}

// ---------------- fused conv_x + router ----------------
__global__ void conv_x_router_kernel(const float* __restrict__ x,
                                     const float* __restrict__ wr) {
    int t = blockIdx.x;
    int tid = threadIdx.x, w = tid >> 5, lane = tid & 31;
    if (blockIdx.x == 0 && tid < EE) g_cnt[tid] = 0;

    float4 v = ((const float4*)(x + (size_t)t * DD))[tid];
    ((uint2*)g_xh)[(size_t)t * 256 + tid] = pack_hi(v);

    const float* xr = x + (size_t)t * DD;
    const float* wrow = wr + (size_t)w * DD;
    float s = 0.f;
    for (int d = lane; d < DD; d += 32) s += xr[d] * wrow[d];
    #pragma unroll
    for (int o = 16; o; o >>= 1) s += __shfl_xor_sync(0xffffffffu, s, o);
    __shared__ float lg[EE];
    if (lane == 0) lg[w] = s;
    __syncthreads();
    if (tid == 0) {
        int i0 = 0; float m0 = lg[0];
        #pragma unroll
        for (int j = 1; j < EE; ++j) if (lg[j] > m0) { m0 = lg[j]; i0 = j; }
        int i1 = -1; float m1 = -INFINITY;
        #pragma unroll
        for (int j = 0; j < EE; ++j) if (j != i0 && lg[j] > m1) { m1 = lg[j]; i1 = j; }
        float w0 = 1.f / (1.f + expf(m1 - m0));
        float w1 = 1.f - w0;
        int p0 = atomicAdd(&g_cnt[i0], 1);
        g_tok[i0 * CAP + p0] = t; g_wt[i0 * CAP + p0] = w0;
        int p1 = atomicAdd(&g_cnt[i1], 1);
        g_tok[i1 * CAP + p1] = t; g_wt[i1 * CAP + p1] = w1;
    }
}

// ---------------- weight conversion kernels (MLP-boosted) ----------------
// conv_wgu: block handles 4 interleaved-rows; 4 independent LDG.128 per thread.
__global__ void conv_wgu_kernel(const float* __restrict__ Wg, const float* __restrict__ Wu,
                                const float* __restrict__ sg, const float* __restrict__ su) {
    int b4 = blockIdx.x;                                // 2304 blocks, 4 rows each
    float4 v[4];
    const float* srcs[4];
    #pragma unroll
    for (int jj = 0; jj < 4; ++jj) {
        int b = b4 * 4 + jj;
        int e = b >> 12, r = b & 4095;
        if (e < EE) srcs[jj] = ((r & 1) ? Wu : Wg) + ((size_t)e * HH + (size_t)(r >> 1)) * DD;
        else        srcs[jj] = ((r & 1) ? su : sg) + (size_t)(r >> 1) * DD;
    }
    #pragma unroll
    for (int jj = 0; jj < 4; ++jj) v[jj] = ((const float4*)srcs[jj])[threadIdx.x];
    #pragma unroll
    for (int jj = 0; jj < 4; ++jj)
        ((uint2*)g_wgu)[(size_t)(b4 * 4 + jj) * 256 + threadIdx.x] = pack_hi(v[jj]);
}
// conv_wd: block handles 2 rows; 2 independent LDG.128 per thread.
__global__ void conv_wd_kernel(const float* __restrict__ Wd, const float* __restrict__ sd) {
    int b2 = blockIdx.x;                                // 4608 blocks, 512 thr, 2 rows
    float4 v[2];
    const float* srcs[2];
    #pragma unroll
    for (int jj = 0; jj < 2; ++jj) {
        int b = b2 * 2 + jj;
        int e = b >> 10, d = b & 1023;
        srcs[jj] = (e < EE) ? Wd + ((size_t)e * DD + (size_t)d) * HH
                            : sd + (size_t)d * HH;
    }
    #pragma unroll
    for (int jj = 0; jj < 2; ++jj) v[jj] = ((const float4*)srcs[jj])[threadIdx.x];
    #pragma unroll
    for (int jj = 0; jj < 2; ++jj)
        ((uint2*)g_wd)[(size_t)(b2 * 2 + jj) * 512 + threadIdx.x] = pack_hi(v[jj]);
}

// ---------------- consumer machinery (R12 verbatim) ----------------
#define FRAG_SETUP() \
    int wm = wid & 3, wn = wid >> 2; \
    int ks0 = (wid >> 2) << 1; \
    int lr = lane & 15, lkb = lane >> 4; \
    u32 fsw = (u32)((lr & 7) << 4); \
    u32 baseA[2], baseB[4]; \
    _Pragma("unroll") \
    for (int tm = 0; tm < 2; ++tm) \
        baseA[tm] = (u32)((wm * 32 + tm * 16 + lr) * 128 + lkb * 16); \
    _Pragma("unroll") \
    for (int nb = 0; nb < 4; ++nb) \
        baseB[nb] = (u32)(S_B + (wn * 64 + nb * 16 + lr) * 128 + lkb * 16); \
    float acc[2][8][4]; \
    _Pragma("unroll") \
    for (int a_ = 0; a_ < 2; ++a_) \
        _Pragma("unroll") \
        for (int b_ = 0; b_ < 8; ++b_) \
            _Pragma("unroll") \
            for (int c_ = 0; c_ < 4; ++c_) acc[a_][b_][c_] = 0.f;

#define CONSUME(cur) \
    _Pragma("unroll") \
    for (int i_ = 0; i_ < 4; ++i_) { \
        int ks = (ks0 + i_) & 3; \
        u32 af[2][4], bf[4][4]; \
        _Pragma("unroll") \
        for (int tm = 0; tm < 2; ++tm) \
            ldsm4(af[tm], (cur) + ((baseA[tm] + ks * 32) ^ fsw)); \
        _Pragma("unroll") \
        for (int nb = 0; nb < 4; ++nb) \
            ldsm4(bf[nb], (cur) + ((baseB[nb] + ks * 32) ^ fsw)); \
        _Pragma("unroll") \
        for (int mt = 0; mt < 2; ++mt) \
            _Pragma("unroll") \
            for (int nb = 0; nb < 4; ++nb) { \
                mma16816(acc[mt][nb * 2],     af[mt], bf[nb][0], bf[nb][2]); \
                mma16816(acc[mt][nb * 2 + 1], af[mt], bf[nb][1], bf[nb][3]); \
            } \
    }

#define MAINLOOP(NC) \
    ISSUE(0); CP_COMMIT(); \
    ISSUE(1); CP_COMMIT(); \
    for (int kt = 0; kt < (NC); ++kt) { \
        CP_WAIT(1); \
        __syncthreads(); \
        if (kt + 2 < (NC)) ISSUE(kt + 2); \
        CP_COMMIT(); \
        u32 cur = sb + (u32)(kt % NSTAGE) * STG; \
        CONSUME(cur); \
    }

// =====================================================================
// GEMM1: C[128,128] = Xg[128,1024] . Wgu^T ; epilogue SwiGLU -> g_hh
// =====================================================================
__global__ void __launch_bounds__(256, 2)
gemm1_kernel() {
    int e = blockIdx.z;
    int ne = (e == EE) ? T_TOK : g_cnt[e];
    int mbase = blockIdx.y * BM;
    if (mbase >= ne) return;
    int ntile = blockIdx.x;

    extern __shared__ char smem[];
    u32 sb = smem_u32(smem);
    __shared__ int s_tok[128];
    int tid = threadIdx.x, wid = tid >> 5, lane = tid & 31;
    if (tid < 128) {
        int r = mbase + tid;
        s_tok[tid] = (e == EE) ? r : ((r < ne) ? g_tok[e * CAP + r] : g_tok[e * CAP]);
    }
    __syncthreads();

    int pw = tid >> 5, psub = (tid >> 3) & 3, pc = tid & 7;
    u32 sOff[4];
    const __half* aSrc[4];
    #pragma unroll
    for (int j = 0; j < 4; ++j) {
        int r = pw * 16 + j * 4 + psub;
        sOff[j] = ((u32)(r * 128 + pc * 16)) ^ ((u32)((r & 7) << 4));
        aSrc[j] = g_xh + (size_t)s_tok[r] * DD + pc * 8;
    }
    const __half* bSrc = g_wgu + (size_t)(e * 4096 + ntile * BN + pw * 16 + psub) * DD + pc * 8;

#define ISSUE(s) do { \
    u32 _st = sb + (u32)((s) % NSTAGE) * STG; \
    _Pragma("unroll") \
    for (int j = 0; j < 4; ++j) cpa16(_st + sOff[j], aSrc[j] + (s) * BK); \
    _Pragma("unroll") \
    for (int j = 0; j < 4; ++j) cpa16(_st + S_B + sOff[j], bSrc + j * 4 * DD + (s) * BK); \
} while (0)

    FRAG_SETUP();
    MAINLOOP(DD / BK);   // 16 chunks
#undef ISSUE

    size_t slotBase = (size_t)e * CAP + mbase;
    int rbase = wm * 32 + (lane >> 2), cquad = lane & 3;
    #pragma unroll
    for (int mt = 0; mt < 2; ++mt)
        #pragma unroll
        for (int nt = 0; nt < 8; ++nt) {
            int hcol = ntile * 64 + wn * 32 + nt * 4 + cquad;
            float* c = acc[mt][nt];
            #pragma unroll
            for (int half = 0; half < 2; ++half) {
                int r = rbase + mt * 16 + half * 8;
                float gv = c[half * 2], uv = c[half * 2 + 1];
                float h = (gv / (1.f + __expf(-gv))) * uv;
                g_hh[(slotBase + (size_t)r) * HH + (size_t)hcol] = __float2half_rn(h);
            }
        }
}

// =====================================================================
// GEMM2 shared expert: full K; plain STG (covers every out element once)
// =====================================================================
__global__ void __launch_bounds__(256, 2)
gemm2s_kernel(float* __restrict__ out) {
    int mbase = blockIdx.y * BM;
    int ntile = blockIdx.x;

    extern __shared__ char smem[];
    u32 sb = smem_u32(smem);
    int tid = threadIdx.x, wid = tid >> 5, lane = tid & 31;

    size_t slotBase = (size_t)EE * CAP + mbase;

    int pw = tid >> 5, psub = (tid >> 3) & 3, pc = tid & 7;
    u32 sOff[4];
    #pragma unroll
    for (int j = 0; j < 4; ++j) {
        int r = pw * 16 + j * 4 + psub;
        sOff[j] = ((u32)(r * 128 + pc * 16)) ^ ((u32)((r & 7) << 4));
    }
    const __half* aSrc = g_hh + (slotBase + (size_t)(pw * 16 + psub)) * HH + pc * 8;
    const __half* bSrc = g_wd + (size_t)(EE * DD + ntile * BN + pw * 16 + psub) * HH + pc * 8;

#define ISSUE(s) do { \
    u32 _st = sb + (u32)((s) % NSTAGE) * STG; \
    _Pragma("unroll") \
    for (int j = 0; j < 4; ++j) cpa16(_st + sOff[j], aSrc + j * 4 * HH + (s) * BK); \
    _Pragma("unroll") \
    for (int j = 0; j < 4; ++j) cpa16(_st + S_B + sOff[j], bSrc + j * 4 * HH + (s) * BK); \
} while (0)

    FRAG_SETUP();
    MAINLOOP(HH / BK);  // 32 chunks, full K
#undef ISSUE

    // epilogue: direct store (token = slot row; weight = 1)
    int rbase = wm * 32 + (lane >> 2), cquad = lane & 3;
    #pragma unroll
    for (int mt = 0; mt < 2; ++mt)
        #pragma unroll
        for (int nt = 0; nt < 8; ++nt) {
            int col = ntile * BN + wn * 64 + nt * 8 + cquad * 2;
            float* c = acc[mt][nt];
            #pragma unroll
            for (int half = 0; half < 2; ++half) {
                int r = rbase + mt * 16 + half * 8;
                float* orow = out + (size_t)(mbase + r) * DD + col;
                orow[0] = c[half * 2];
                orow[1] = c[half * 2 + 1];
            }
        }
}

// =====================================================================
// GEMM2 routed: full K; weighted atomic scatter on top of shared output
// =====================================================================
__global__ void __launch_bounds__(256, 2)
gemm2r_kernel(float* __restrict__ out) {
    int e = blockIdx.z;
    int ne = g_cnt[e];
    int mbase = blockIdx.y * BM;
    if (mbase >= ne) return;
    int ntile = blockIdx.x;

    extern __shared__ char smem[];
    u32 sb = smem_u32(smem);
    __shared__ int   s_tok[128];
    __shared__ float s_wt[128];
    int tid = threadIdx.x, wid = tid >> 5, lane = tid & 31;
    if (tid < 128) {
        int r = mbase + tid;
        if (r < ne) { s_tok[tid] = g_tok[e * CAP + r]; s_wt[tid] = g_wt[e * CAP + r]; }
        else        { s_tok[tid] = 0; s_wt[tid] = 0.f; }
    }
    __syncthreads();

    size_t slotBase = (size_t)e * CAP + mbase;

    int pw = tid >> 5, psub = (tid >> 3) & 3, pc = tid & 7;
    u32 sOff[4];
    #pragma unroll
    for (int j = 0; j < 4; ++j) {
        int r = pw * 16 + j * 4 + psub;
        sOff[j] = ((u32)(r * 128 + pc * 16)) ^ ((u32)((r & 7) << 4));
    }
    const __half* aSrc = g_hh + (slotBase + (size_t)(pw * 16 + psub)) * HH + pc * 8;
    const __half* bSrc = g_wd + (size_t)(e * DD + ntile * BN + pw * 16 + psub) * HH + pc * 8;

#define ISSUE(s) do { \
    u32 _st = sb + (u32)((s) % NSTAGE) * STG; \
    _Pragma("unroll") \
    for (int j = 0; j < 4; ++j) cpa16(_st + sOff[j], aSrc + j * 4 * HH + (s) * BK); \
    _Pragma("unroll") \
    for (int j = 0; j < 4; ++j) cpa16(_st + S_B + sOff[j], bSrc + j * 4 * HH + (s) * BK); \
} while (0)

    FRAG_SETUP();
    MAINLOOP(HH / BK);  // 32 chunks, full K
#undef ISSUE

    int nv = ne - mbase; if (nv > BM) nv = BM;
    int rbase = wm * 32 + (lane >> 2), cquad = lane & 3;
    #pragma unroll
    for (int mt = 0; mt < 2; ++mt)
        #pragma unroll
        for (int nt = 0; nt < 8; ++nt) {
            int col = ntile * BN + wn * 64 + nt * 8 + cquad * 2;
            float* c = acc[mt][nt];
            #pragma unroll
            for (int half = 0; half < 2; ++half) {
                int r = rbase + mt * 16 + half * 8;
                if (r < nv) {
                    int tok = s_tok[r]; float wt = s_wt[r];
                    float* orow = out + (size_t)tok * DD + col;
                    atomicAdd(orow,     wt * c[half * 2]);
                    atomicAdd(orow + 1, wt * c[half * 2 + 1]);
                }
            }
        }
}

// ---------------- launch ----------------
extern "C" void kernel_launch(void* const* d_in, const int* in_sizes, int n_in,
                              void* d_out, int out_size) {
    const float* x  = (const float*)d_in[0];
    const float* wr = (const float*)d_in[1];
    const float* Wg = (const float*)d_in[2];
    const float* Wu = (const float*)d_in[3];
    const float* Wd = (const float*)d_in[4];
    const float* sg = (const float*)d_in[5];
    const float* su = (const float*)d_in[6];
    const float* sd = (const float*)d_in[7];
    float* out = (float*)d_out;

    cudaFuncSetAttribute(gemm1_kernel,  cudaFuncAttributeMaxDynamicSharedMemorySize, SMEM_DYN);
    cudaFuncSetAttribute(gemm2s_kernel, cudaFuncAttributeMaxDynamicSharedMemorySize, SMEM_DYN);
    cudaFuncSetAttribute(gemm2r_kernel, cudaFuncAttributeMaxDynamicSharedMemorySize, SMEM_DYN);

    // gemm1 stays launch #4 (ncu slot)
    conv_x_router_kernel<<<T_TOK, 256>>>(x, wr);
    conv_wgu_kernel<<<NEXP * 4096 / 4, 256>>>(Wg, Wu, sg, su);
    conv_wd_kernel<<<NEXP * DD / 2, 512>>>(Wd, sd);

    dim3 g1(32, 32, NEXP);
    gemm1_kernel<<<g1, 256, SMEM_DYN>>>();

    dim3 g2s(8, 32);               // shared expert: STG, replaces zeroing
    gemm2s_kernel<<<g2s, 256, SMEM_DYN>>>(out);

    dim3 g2r(8, 32, EE);           // routed experts: atomic add
    gemm2r_kernel<<<g2r, 256, SMEM_DYN>>>(out);
}

// round 16
// speedup vs baseline: 1.2439x; 1.0094x over previous
#include <cuda_runtime.h>
#include <cuda_fp16.h>
#include <cstdint>
#include <math.h>

// ---------------- problem constants ----------------
#define T_TOK 4096
#define DD    1024
#define HH    2048
#define EE    8
#define CAP   4096
#define NEXP  9          // 8 routed + shared as "expert 8"

// ---------------- tile config (R12/R14, proven best) ----------------
#define BM 128
#define BN 128
#define BK 64            // k halfs per chunk (128B rows -> SW128)
#define NSTAGE 3
#define S_B   16384      // B plane offset inside a stage
#define STG   32768      // stage bytes: A 16KB + B 16KB
#define SMEM_DYN (NSTAGE * STG)   // 98304

typedef unsigned int u32;
typedef unsigned long long u64;

// ---------------- device scratch ----------------
__device__ int   g_cnt[EE];
__device__ int   g_tok[EE * CAP];
__device__ float g_wt [EE * CAP];
__device__ __half g_xh [(size_t)T_TOK * DD];
__device__ __half g_wgu[(size_t)NEXP * 4096 * DD];   // interleaved gate/up rows
__device__ __half g_wd [(size_t)NEXP * DD * HH];
__device__ __half g_hh [(size_t)NEXP * CAP * HH];

// ---------------- helpers ----------------
__device__ __forceinline__ u32 smem_u32(const void* p) {
    u32 a; asm("{ .reg .u64 t; cvta.to.shared.u64 t, %1; cvt.u32.u64 %0, t; }" : "=r"(a) : "l"(p));
    return a;
}
__device__ __forceinline__ void cpa16(u32 dst, const void* gsrc) {
    asm volatile("cp.async.cg.shared.global [%0], [%1], 16;" :: "r"(dst), "l"(gsrc) : "memory");
}
#define CP_COMMIT() asm volatile("cp.async.commit_group;" ::: "memory")
#define CP_WAIT(n)  asm volatile("cp.async.wait_group %0;" :: "n"(n) : "memory")

__device__ __forceinline__ void ldsm4(u32* r, u32 addr) {
    asm volatile("ldmatrix.sync.aligned.m8n8.x4.shared.b16 {%0,%1,%2,%3}, [%4];"
        : "=r"(r[0]), "=r"(r[1]), "=r"(r[2]), "=r"(r[3]) : "r"(addr));
}
__device__ __forceinline__ void mma16816(float* c, const u32* a, u32 b0, u32 b1) {
    asm volatile("mma.sync.aligned.m16n8k16.row.col.f32.f16.f16.f32 "
        "{%0,%1,%2,%3}, {%4,%5,%6,%7}, {%8,%9}, {%0,%1,%2,%3};"
        : "+f"(c[0]), "+f"(c[1]), "+f"(c[2]), "+f"(c[3])
        : "r"(a[0]), "r"(a[1]), "r"(a[2]), "r"(a[3]), "r"(b0), "r"(b1));
}
__device__ __forceinline__ void red2(float* addr, float v0, float v1) {
    asm volatile("red.global.add.v2.f32 [%0], {%1,%2};"
        :: "l"(addr), "f"(v0), "f"(v1) : "memory");
}
__device__ __forceinline__ uint2 pack_hi(float4 v) {
    __half2 h0 = __floats2half2_rn(v.x, v.y);
    __half2 h1 = __floats2half2_rn(v.z, v.w);
    uint2 r; r.x = *(u32*)&h0; r.y = *(u32*)&h1; return r;
}

// ---------------- fused conv_x + router (x read ONCE via smem stage) ----------------
__global__ void conv_x_router_kernel(const float* __restrict__ x,
                                     const float* __restrict__ wr) {
    __shared__ float sx[DD];
    __shared__ float lg[EE];
    int t = blockIdx.x;
    int tid = threadIdx.x, w = tid >> 5, lane = tid & 31;
    if (blockIdx.x == 0 && tid < EE) g_cnt[tid] = 0;

    float4 v = ((const float4*)(x + (size_t)t * DD))[tid];
    ((float4*)sx)[tid] = v;
    ((uint2*)g_xh)[(size_t)t * 256 + tid] = pack_hi(v);
    __syncthreads();

    const float* wrow = wr + (size_t)w * DD;
    float s = 0.f;
    for (int d = lane; d < DD; d += 32) s += sx[d] * wrow[d];
    #pragma unroll
    for (int o = 16; o; o >>= 1) s += __shfl_xor_sync(0xffffffffu, s, o);
    if (lane == 0) lg[w] = s;
    __syncthreads();
    if (tid == 0) {
        int i0 = 0; float m0 = lg[0];
        #pragma unroll
        for (int j = 1; j < EE; ++j) if (lg[j] > m0) { m0 = lg[j]; i0 = j; }
        int i1 = -1; float m1 = -INFINITY;
        #pragma unroll
        for (int j = 0; j < EE; ++j) if (j != i0 && lg[j] > m1) { m1 = lg[j]; i1 = j; }
        float w0 = 1.f / (1.f + expf(m1 - m0));
        float w1 = 1.f - w0;
        int p0 = atomicAdd(&g_cnt[i0], 1);
        g_tok[i0 * CAP + p0] = t; g_wt[i0 * CAP + p0] = w0;
        int p1 = atomicAdd(&g_cnt[i1], 1);
        g_tok[i1 * CAP + p1] = t; g_wt[i1 * CAP + p1] = w1;
    }
}

// ---------------- weight conversion kernels (MLP-boosted, R15) ----------------
__global__ void conv_wgu_kernel(const float* __restrict__ Wg, const float* __restrict__ Wu,
                                const float* __restrict__ sg, const float* __restrict__ su) {
    int b4 = blockIdx.x;
    float4 v[4];
    const float* srcs[4];
    #pragma unroll
    for (int jj = 0; jj < 4; ++jj) {
        int b = b4 * 4 + jj;
        int e = b >> 12, r = b & 4095;
        if (e < EE) srcs[jj] = ((r & 1) ? Wu : Wg) + ((size_t)e * HH + (size_t)(r >> 1)) * DD;
        else        srcs[jj] = ((r & 1) ? su : sg) + (size_t)(r >> 1) * DD;
    }
    #pragma unroll
    for (int jj = 0; jj < 4; ++jj) v[jj] = ((const float4*)srcs[jj])[threadIdx.x];
    #pragma unroll
    for (int jj = 0; jj < 4; ++jj)
        ((uint2*)g_wgu)[(size_t)(b4 * 4 + jj) * 256 + threadIdx.x] = pack_hi(v[jj]);
}
__global__ void conv_wd_kernel(const float* __restrict__ Wd, const float* __restrict__ sd) {
    int b2 = blockIdx.x;
    float4 v[2];
    const float* srcs[2];
    #pragma unroll
    for (int jj = 0; jj < 2; ++jj) {
        int b = b2 * 2 + jj;
        int e = b >> 10, d = b & 1023;
        srcs[jj] = (e < EE) ? Wd + ((size_t)e * DD + (size_t)d) * HH
                            : sd + (size_t)d * HH;
    }
    #pragma unroll
    for (int jj = 0; jj < 2; ++jj) v[jj] = ((const float4*)srcs[jj])[threadIdx.x];
    #pragma unroll
    for (int jj = 0; jj < 2; ++jj)
        ((uint2*)g_wd)[(size_t)(b2 * 2 + jj) * 512 + threadIdx.x] = pack_hi(v[jj]);
}

// ---------------- consumer machinery (R12 verbatim) ----------------
#define FRAG_SETUP() \
    int wm = wid & 3, wn = wid >> 2; \
    int ks0 = (wid >> 2) << 1; \
    int lr = lane & 15, lkb = lane >> 4; \
    u32 fsw = (u32)((lr & 7) << 4); \
    u32 baseA[2], baseB[4]; \
    _Pragma("unroll") \
    for (int tm = 0; tm < 2; ++tm) \
        baseA[tm] = (u32)((wm * 32 + tm * 16 + lr) * 128 + lkb * 16); \
    _Pragma("unroll") \
    for (int nb = 0; nb < 4; ++nb) \
        baseB[nb] = (u32)(S_B + (wn * 64 + nb * 16 + lr) * 128 + lkb * 16); \
    float acc[2][8][4]; \
    _Pragma("unroll") \
    for (int a_ = 0; a_ < 2; ++a_) \
        _Pragma("unroll") \
        for (int b_ = 0; b_ < 8; ++b_) \
            _Pragma("unroll") \
            for (int c_ = 0; c_ < 4; ++c_) acc[a_][b_][c_] = 0.f;

#define CONSUME(cur) \
    _Pragma("unroll") \
    for (int i_ = 0; i_ < 4; ++i_) { \
        int ks = (ks0 + i_) & 3; \
        u32 af[2][4], bf[4][4]; \
        _Pragma("unroll") \
        for (int tm = 0; tm < 2; ++tm) \
            ldsm4(af[tm], (cur) + ((baseA[tm] + ks * 32) ^ fsw)); \
        _Pragma("unroll") \
        for (int nb = 0; nb < 4; ++nb) \
            ldsm4(bf[nb], (cur) + ((baseB[nb] + ks * 32) ^ fsw)); \
        _Pragma("unroll") \
        for (int mt = 0; mt < 2; ++mt) \
            _Pragma("unroll") \
            for (int nb = 0; nb < 4; ++nb) { \
                mma16816(acc[mt][nb * 2],     af[mt], bf[nb][0], bf[nb][2]); \
                mma16816(acc[mt][nb * 2 + 1], af[mt], bf[nb][1], bf[nb][3]); \
            } \
    }

#define MAINLOOP(NC) \
    ISSUE(0); CP_COMMIT(); \
    ISSUE(1); CP_COMMIT(); \
    for (int kt = 0; kt < (NC); ++kt) { \
        CP_WAIT(1); \
        __syncthreads(); \
        if (kt + 2 < (NC)) ISSUE(kt + 2); \
        CP_COMMIT(); \
        u32 cur = sb + (u32)(kt % NSTAGE) * STG; \
        CONSUME(cur); \
    }

// =====================================================================
// GEMM1: C[128,128] = Xg[128,1024] . Wgu^T ; epilogue SwiGLU -> g_hh
// =====================================================================
__global__ void __launch_bounds__(256, 2)
gemm1_kernel() {
    int e = blockIdx.z;
    int ne = (e == EE) ? T_TOK : g_cnt[e];
    int mbase = blockIdx.y * BM;
    if (mbase >= ne) return;
    int ntile = blockIdx.x;

    extern __shared__ char smem[];
    u32 sb = smem_u32(smem);
    __shared__ int s_tok[128];
    int tid = threadIdx.x, wid = tid >> 5, lane = tid & 31;
    if (tid < 128) {
        int r = mbase + tid;
        s_tok[tid] = (e == EE) ? r : ((r < ne) ? g_tok[e * CAP + r] : g_tok[e * CAP]);
    }
    __syncthreads();

    int pw = tid >> 5, psub = (tid >> 3) & 3, pc = tid & 7;
    u32 sOff[4];
    const __half* aSrc[4];
    #pragma unroll
    for (int j = 0; j < 4; ++j) {
        int r = pw * 16 + j * 4 + psub;
        sOff[j] = ((u32)(r * 128 + pc * 16)) ^ ((u32)((r & 7) << 4));
        aSrc[j] = g_xh + (size_t)s_tok[r] * DD + pc * 8;
    }
    const __half* bSrc = g_wgu + (size_t)(e * 4096 + ntile * BN + pw * 16 + psub) * DD + pc * 8;

#define ISSUE(s) do { \
    u32 _st = sb + (u32)((s) % NSTAGE) * STG; \
    _Pragma("unroll") \
    for (int j = 0; j < 4; ++j) cpa16(_st + sOff[j], aSrc[j] + (s) * BK); \
    _Pragma("unroll") \
    for (int j = 0; j < 4; ++j) cpa16(_st + S_B + sOff[j], bSrc + j * 4 * DD + (s) * BK); \
} while (0)

    FRAG_SETUP();
    MAINLOOP(DD / BK);   // 16 chunks
#undef ISSUE

    size_t slotBase = (size_t)e * CAP + mbase;
    int rbase = wm * 32 + (lane >> 2), cquad = lane & 3;
    #pragma unroll
    for (int mt = 0; mt < 2; ++mt)
        #pragma unroll
        for (int nt = 0; nt < 8; ++nt) {
            int hcol = ntile * 64 + wn * 32 + nt * 4 + cquad;
            float* c = acc[mt][nt];
            #pragma unroll
            for (int half = 0; half < 2; ++half) {
                int r = rbase + mt * 16 + half * 8;
                float gv = c[half * 2], uv = c[half * 2 + 1];
                float h = (gv / (1.f + __expf(-gv))) * uv;
                g_hh[(slotBase + (size_t)r) * HH + (size_t)hcol] = __float2half_rn(h);
            }
        }
}

// =====================================================================
// GEMM2 shared expert: full K; plain float2 STG (covers out exactly once)
// =====================================================================
__global__ void __launch_bounds__(256, 2)
gemm2s_kernel(float* __restrict__ out) {
    int mbase = blockIdx.y * BM;
    int ntile = blockIdx.x;

    extern __shared__ char smem[];
    u32 sb = smem_u32(smem);
    int tid = threadIdx.x, wid = tid >> 5, lane = tid & 31;

    size_t slotBase = (size_t)EE * CAP + mbase;

    int pw = tid >> 5, psub = (tid >> 3) & 3, pc = tid & 7;
    u32 sOff[4];
    #pragma unroll
    for (int j = 0; j < 4; ++j) {
        int r = pw * 16 + j * 4 + psub;
        sOff[j] = ((u32)(r * 128 + pc * 16)) ^ ((u32)((r & 7) << 4));
    }
    const __half* aSrc = g_hh + (slotBase + (size_t)(pw * 16 + psub)) * HH + pc * 8;
    const __half* bSrc = g_wd + (size_t)(EE * DD + ntile * BN + pw * 16 + psub) * HH + pc * 8;

#define ISSUE(s) do { \
    u32 _st = sb + (u32)((s) % NSTAGE) * STG; \
    _Pragma("unroll") \
    for (int j = 0; j < 4; ++j) cpa16(_st + sOff[j], aSrc + j * 4 * HH + (s) * BK); \
    _Pragma("unroll") \
    for (int j = 0; j < 4; ++j) cpa16(_st + S_B + sOff[j], bSrc + j * 4 * HH + (s) * BK); \
} while (0)

    FRAG_SETUP();
    MAINLOOP(HH / BK);  // 32 chunks, full K
#undef ISSUE

    int rbase = wm * 32 + (lane >> 2), cquad = lane & 3;
    #pragma unroll
    for (int mt = 0; mt < 2; ++mt)
        #pragma unroll
        for (int nt = 0; nt < 8; ++nt) {
            int col = ntile * BN + wn * 64 + nt * 8 + cquad * 2;
            float* c = acc[mt][nt];
            #pragma unroll
            for (int half = 0; half < 2; ++half) {
                int r = rbase + mt * 16 + half * 8;
                *(float2*)(out + (size_t)(mbase + r) * DD + col) =
                    make_float2(c[half * 2], c[half * 2 + 1]);
            }
        }
}

// =====================================================================
// GEMM2 routed: full K; weighted vector-red scatter on top of shared out
// =====================================================================
__global__ void __launch_bounds__(256, 2)
gemm2r_kernel(float* __restrict__ out) {
    int e = blockIdx.z;
    int ne = g_cnt[e];
    int mbase = blockIdx.y * BM;
    if (mbase >= ne) return;
    int ntile = blockIdx.x;

    extern __shared__ char smem[];
    u32 sb = smem_u32(smem);
    __shared__ int   s_tok[128];
    __shared__ float s_wt[128];
    int tid = threadIdx.x, wid = tid >> 5, lane = tid & 31;
    if (tid < 128) {
        int r = mbase + tid;
        if (r < ne) { s_tok[tid] = g_tok[e * CAP + r]; s_wt[tid] = g_wt[e * CAP + r]; }
        else        { s_tok[tid] = 0; s_wt[tid] = 0.f; }
    }
    __syncthreads();

    size_t slotBase = (size_t)e * CAP + mbase;

    int pw = tid >> 5, psub = (tid >> 3) & 3, pc = tid & 7;
    u32 sOff[4];
    #pragma unroll
    for (int j = 0; j < 4; ++j) {
        int r = pw * 16 + j * 4 + psub;
        sOff[j] = ((u32)(r * 128 + pc * 16)) ^ ((u32)((r & 7) << 4));
    }
    const __half* aSrc = g_hh + (slotBase + (size_t)(pw * 16 + psub)) * HH + pc * 8;
    const __half* bSrc = g_wd + (size_t)(e * DD + ntile * BN + pw * 16 + psub) * HH + pc * 8;

#define ISSUE(s) do { \
    u32 _st = sb + (u32)((s) % NSTAGE) * STG; \
    _Pragma("unroll") \
    for (int j = 0; j < 4; ++j) cpa16(_st + sOff[j], aSrc + j * 4 * HH + (s) * BK); \
    _Pragma("unroll") \
    for (int j = 0; j < 4; ++j) cpa16(_st + S_B + sOff[j], bSrc + j * 4 * HH + (s) * BK); \
} while (0)

    FRAG_SETUP();
    MAINLOOP(HH / BK);  // 32 chunks, full K
#undef ISSUE

    int nv = ne - mbase; if (nv > BM) nv = BM;
    int rbase = wm * 32 + (lane >> 2), cquad = lane & 3;
    #pragma unroll
    for (int mt = 0; mt < 2; ++mt)
        #pragma unroll
        for (int nt = 0; nt < 8; ++nt) {
            int col = ntile * BN + wn * 64 + nt * 8 + cquad * 2;
            float* c = acc[mt][nt];
            #pragma unroll
            for (int half = 0; half < 2; ++half) {
                int r = rbase + mt * 16 + half * 8;
                if (r < nv) {
                    int tok = s_tok[r]; float wt = s_wt[r];
                    red2(out + (size_t)tok * DD + col,
                         wt * c[half * 2], wt * c[half * 2 + 1]);
                }
            }
        }
}

// ---------------- launch ----------------
extern "C" void kernel_launch(void* const* d_in, const int* in_sizes, int n_in,
                              void* d_out, int out_size) {
    const float* x  = (const float*)d_in[0];
    const float* wr = (const float*)d_in[1];
    const float* Wg = (const float*)d_in[2];
    const float* Wu = (const float*)d_in[3];
    const float* Wd = (const float*)d_in[4];
    const float* sg = (const float*)d_in[5];
    const float* su = (const float*)d_in[6];
    const float* sd = (const float*)d_in[7];
    float* out = (float*)d_out;

    cudaFuncSetAttribute(gemm1_kernel,  cudaFuncAttributeMaxDynamicSharedMemorySize, SMEM_DYN);
    cudaFuncSetAttribute(gemm2s_kernel, cudaFuncAttributeMaxDynamicSharedMemorySize, SMEM_DYN);
    cudaFuncSetAttribute(gemm2r_kernel, cudaFuncAttributeMaxDynamicSharedMemorySize, SMEM_DYN);

    // gemm1 stays launch #4 (ncu slot)
    conv_x_router_kernel<<<T_TOK, 256>>>(x, wr);
    conv_wgu_kernel<<<NEXP * 4096 / 4, 256>>>(Wg, Wu, sg, su);
    conv_wd_kernel<<<NEXP * DD / 2, 512>>>(Wd, sd);

    dim3 g1(32, 32, NEXP);
    gemm1_kernel<<<g1, 256, SMEM_DYN>>>();

    dim3 g2s(8, 32);               // shared expert: STG, replaces zeroing
    gemm2s_kernel<<<g2s, 256, SMEM_DYN>>>(out);

    dim3 g2r(8, 32, EE);           // routed experts: vector red
    gemm2r_kernel<<<g2r, 256, SMEM_DYN>>>(out);
}

// round 17
// speedup vs baseline: 1.2441x; 1.0002x over previous
#include <cuda_runtime.h>
#include <cuda_fp16.h>
#include <cstdint>
#include <math.h>

// ---------------- problem constants ----------------
#define T_TOK 4096
#define DD    1024
#define HH    2048
#define EE    8
#define CAP   4096
#define NEXP  9          // 8 routed + shared as "expert 8"

// ---------------- tile config (R12/R14, proven best) ----------------
#define BM 128
#define BN 128
#define BK 64            // k halfs per chunk (128B rows -> SW128)
#define NSTAGE 3
#define S_B   16384      // B plane offset inside a stage
#define STG   32768      // stage bytes: A 16KB + B 16KB
#define SMEM_DYN (NSTAGE * STG)   // 98304

typedef unsigned int u32;
typedef unsigned long long u64;

// ---------------- device scratch ----------------
__device__ int   g_cnt[EE];
__device__ int   g_tok[EE * CAP];
__device__ float g_wt [EE * CAP];
__device__ __half g_xh [(size_t)T_TOK * DD];
__device__ __half g_wgu[(size_t)NEXP * 4096 * DD];   // interleaved gate/up rows
__device__ __half g_wd [(size_t)NEXP * DD * HH];
__device__ __half g_hh [(size_t)NEXP * CAP * HH];

// ---------------- helpers ----------------
__device__ __forceinline__ u32 smem_u32(const void* p) {
    u32 a; asm("{ .reg .u64 t; cvta.to.shared.u64 t, %1; cvt.u32.u64 %0, t; }" : "=r"(a) : "l"(p));
    return a;
}
__device__ __forceinline__ void cpa16(u32 dst, const void* gsrc) {
    asm volatile("cp.async.cg.shared.global [%0], [%1], 16;" :: "r"(dst), "l"(gsrc) : "memory");
}
#define CP_COMMIT() asm volatile("cp.async.commit_group;" ::: "memory")
#define CP_WAIT(n)  asm volatile("cp.async.wait_group %0;" :: "n"(n) : "memory")

__device__ __forceinline__ void ldsm4(u32* r, u32 addr) {
    asm volatile("ldmatrix.sync.aligned.m8n8.x4.shared.b16 {%0,%1,%2,%3}, [%4];"
        : "=r"(r[0]), "=r"(r[1]), "=r"(r[2]), "=r"(r[3]) : "r"(addr));
}
__device__ __forceinline__ void mma16816(float* c, const u32* a, u32 b0, u32 b1) {
    asm volatile("mma.sync.aligned.m16n8k16.row.col.f32.f16.f16.f32 "
        "{%0,%1,%2,%3}, {%4,%5,%6,%7}, {%8,%9}, {%0,%1,%2,%3};"
        : "+f"(c[0]), "+f"(c[1]), "+f"(c[2]), "+f"(c[3])
        : "r"(a[0]), "r"(a[1]), "r"(a[2]), "r"(a[3]), "r"(b0), "r"(b1));
}
__device__ __forceinline__ void red2(float* addr, float v0, float v1) {
    asm volatile("red.global.add.v2.f32 [%0], {%1,%2};"
        :: "l"(addr), "f"(v0), "f"(v1) : "memory");
}
__device__ __forceinline__ uint2 pack_hi(float4 v) {
    __half2 h0 = __floats2half2_rn(v.x, v.y);
    __half2 h1 = __floats2half2_rn(v.z, v.w);
    uint2 r; r.x = *(u32*)&h0; r.y = *(u32*)&h1; return r;
}

// ---------------- fused conv_x + router (x read ONCE via smem stage) ----------------
__global__ void conv_x_router_kernel(const float* __restrict__ x,
                                     const float* __restrict__ wr) {
    __shared__ float sx[DD];
    __shared__ float lg[EE];
    int t = blockIdx.x;
    int tid = threadIdx.x, w = tid >> 5, lane = tid & 31;
    if (blockIdx.x == 0 && tid < EE) g_cnt[tid] = 0;

    float4 v = ((const float4*)(x + (size_t)t * DD))[tid];
    ((float4*)sx)[tid] = v;
    ((uint2*)g_xh)[(size_t)t * 256 + tid] = pack_hi(v);
    __syncthreads();

    const float* wrow = wr + (size_t)w * DD;
    float s = 0.f;
    for (int d = lane; d < DD; d += 32) s += sx[d] * wrow[d];
    #pragma unroll
    for (int o = 16; o; o >>= 1) s += __shfl_xor_sync(0xffffffffu, s, o);
    if (lane == 0) lg[w] = s;
    __syncthreads();
    if (tid == 0) {
        int i0 = 0; float m0 = lg[0];
        #pragma unroll
        for (int j = 1; j < EE; ++j) if (lg[j] > m0) { m0 = lg[j]; i0 = j; }
        int i1 = -1; float m1 = -INFINITY;
        #pragma unroll
        for (int j = 0; j < EE; ++j) if (j != i0 && lg[j] > m1) { m1 = lg[j]; i1 = j; }
        float w0 = 1.f / (1.f + expf(m1 - m0));
        float w1 = 1.f - w0;
        int p0 = atomicAdd(&g_cnt[i0], 1);
        g_tok[i0 * CAP + p0] = t; g_wt[i0 * CAP + p0] = w0;
        int p1 = atomicAdd(&g_cnt[i1], 1);
        g_tok[i1 * CAP + p1] = t; g_wt[i1 * CAP + p1] = w1;
    }
}

// ---------------- weight conversion kernels (MLP-boosted) ----------------
__global__ void conv_wgu_kernel(const float* __restrict__ Wg, const float* __restrict__ Wu,
                                const float* __restrict__ sg, const float* __restrict__ su) {
    int b4 = blockIdx.x;
    float4 v[4];
    const float* srcs[4];
    #pragma unroll
    for (int jj = 0; jj < 4; ++jj) {
        int b = b4 * 4 + jj;
        int e = b >> 12, r = b & 4095;
        if (e < EE) srcs[jj] = ((r & 1) ? Wu : Wg) + ((size_t)e * HH + (size_t)(r >> 1)) * DD;
        else        srcs[jj] = ((r & 1) ? su : sg) + (size_t)(r >> 1) * DD;
    }
    #pragma unroll
    for (int jj = 0; jj < 4; ++jj) v[jj] = ((const float4*)srcs[jj])[threadIdx.x];
    #pragma unroll
    for (int jj = 0; jj < 4; ++jj)
        ((uint2*)g_wgu)[(size_t)(b4 * 4 + jj) * 256 + threadIdx.x] = pack_hi(v[jj]);
}
__global__ void conv_wd_kernel(const float* __restrict__ Wd, const float* __restrict__ sd) {
    int b2 = blockIdx.x;
    float4 v[2];
    const float* srcs[2];
    #pragma unroll
    for (int jj = 0; jj < 2; ++jj) {
        int b = b2 * 2 + jj;
        int e = b >> 10, d = b & 1023;
        srcs[jj] = (e < EE) ? Wd + ((size_t)e * DD + (size_t)d) * HH
                            : sd + (size_t)d * HH;
    }
    #pragma unroll
    for (int jj = 0; jj < 2; ++jj) v[jj] = ((const float4*)srcs[jj])[threadIdx.x];
    #pragma unroll
    for (int jj = 0; jj < 2; ++jj)
        ((uint2*)g_wd)[(size_t)(b2 * 2 + jj) * 512 + threadIdx.x] = pack_hi(v[jj]);
}

// ---------------- consumer machinery (XOR-folded addressing) ----------------
// base bits 5-6 are zero, so (base + ks*32) ^ fsw == (base ^ fsw) ^ (ks*32).
#define FRAG_SETUP() \
    int wm = wid & 3, wn = wid >> 2; \
    int ks0 = (wid >> 2) << 1; \
    int lr = lane & 15, lkb = lane >> 4; \
    u32 fsw = (u32)((lr & 7) << 4); \
    u32 baseA[2], baseB[4]; \
    _Pragma("unroll") \
    for (int tm = 0; tm < 2; ++tm) \
        baseA[tm] = ((u32)((wm * 32 + tm * 16 + lr) * 128 + lkb * 16)) ^ fsw; \
    _Pragma("unroll") \
    for (int nb = 0; nb < 4; ++nb) \
        baseB[nb] = ((u32)(S_B + (wn * 64 + nb * 16 + lr) * 128 + lkb * 16)) ^ fsw; \
    float acc[2][8][4]; \
    _Pragma("unroll") \
    for (int a_ = 0; a_ < 2; ++a_) \
        _Pragma("unroll") \
        for (int b_ = 0; b_ < 8; ++b_) \
            _Pragma("unroll") \
            for (int c_ = 0; c_ < 4; ++c_) acc[a_][b_][c_] = 0.f;

#define CONSUME(cur) \
    _Pragma("unroll") \
    for (int i_ = 0; i_ < 4; ++i_) { \
        int ks = (ks0 + i_) & 3; \
        u32 kx = (u32)(ks << 5); \
        u32 af[2][4], bf[4][4]; \
        _Pragma("unroll") \
        for (int tm = 0; tm < 2; ++tm) \
            ldsm4(af[tm], (cur) + (baseA[tm] ^ kx)); \
        _Pragma("unroll") \
        for (int nb = 0; nb < 4; ++nb) \
            ldsm4(bf[nb], (cur) + (baseB[nb] ^ kx)); \
        _Pragma("unroll") \
        for (int mt = 0; mt < 2; ++mt) \
            _Pragma("unroll") \
            for (int nb = 0; nb < 4; ++nb) { \
                mma16816(acc[mt][nb * 2],     af[mt], bf[nb][0], bf[nb][2]); \
                mma16816(acc[mt][nb * 2 + 1], af[mt], bf[nb][1], bf[nb][3]); \
            } \
    }

#define MAINLOOP(NC) \
    ISSUE(0); CP_COMMIT(); \
    ISSUE(1); CP_COMMIT(); \
    for (int kt = 0; kt < (NC); ++kt) { \
        CP_WAIT(1); \
        __syncthreads(); \
        if (kt + 2 < (NC)) ISSUE(kt + 2); \
        CP_COMMIT(); \
        u32 cur = sb + (u32)(kt % NSTAGE) * STG; \
        CONSUME(cur); \
    }

// =====================================================================
// GEMM1: C[128,128] = Xg[128,1024] . Wgu^T ; epilogue SwiGLU -> g_hh
// =====================================================================
__global__ void __launch_bounds__(256, 2)
gemm1_kernel() {
    int e = blockIdx.z;
    int ne = (e == EE) ? T_TOK : g_cnt[e];
    int mbase = blockIdx.y * BM;
    if (mbase >= ne) return;
    int ntile = blockIdx.x;

    extern __shared__ char smem[];
    u32 sb = smem_u32(smem);
    __shared__ int s_tok[128];
    int tid = threadIdx.x, wid = tid >> 5, lane = tid & 31;
    if (tid < 128) {
        int r = mbase + tid;
        s_tok[tid] = (e == EE) ? r : ((r < ne) ? g_tok[e * CAP + r] : g_tok[e * CAP]);
    }
    __syncthreads();

    int pw = tid >> 5, psub = (tid >> 3) & 3, pc = tid & 7;
    u32 sOff[4];
    const __half* aSrc[4];
    #pragma unroll
    for (int j = 0; j < 4; ++j) {
        int r = pw * 16 + j * 4 + psub;
        sOff[j] = ((u32)(r * 128 + pc * 16)) ^ ((u32)((r & 7) << 4));
        aSrc[j] = g_xh + (size_t)s_tok[r] * DD + pc * 8;
    }
    const __half* bSrc = g_wgu + (size_t)(e * 4096 + ntile * BN + pw * 16 + psub) * DD + pc * 8;

#define ISSUE(s) do { \
    u32 _st = sb + (u32)((s) % NSTAGE) * STG; \
    _Pragma("unroll") \
    for (int j = 0; j < 4; ++j) cpa16(_st + sOff[j], aSrc[j] + (s) * BK); \
    _Pragma("unroll") \
    for (int j = 0; j < 4; ++j) cpa16(_st + S_B + sOff[j], bSrc + j * 4 * DD + (s) * BK); \
} while (0)

    FRAG_SETUP();
    MAINLOOP(DD / BK);   // 16 chunks
#undef ISSUE

    size_t slotBase = (size_t)e * CAP + mbase;
    int rbase = wm * 32 + (lane >> 2), cquad = lane & 3;
    #pragma unroll
    for (int mt = 0; mt < 2; ++mt)
        #pragma unroll
        for (int nt = 0; nt < 8; ++nt) {
            int hcol = ntile * 64 + wn * 32 + nt * 4 + cquad;
            float* c = acc[mt][nt];
            #pragma unroll
            for (int half = 0; half < 2; ++half) {
                int r = rbase + mt * 16 + half * 8;
                float gv = c[half * 2], uv = c[half * 2 + 1];
                float h = (gv / (1.f + __expf(-gv))) * uv;
                g_hh[(slotBase + (size_t)r) * HH + (size_t)hcol] = __float2half_rn(h);
            }
        }
}

// =====================================================================
// GEMM2 shared expert: full K; float2 STG (covers every out element once)
// =====================================================================
__global__ void __launch_bounds__(256, 2)
gemm2s_kernel(float* __restrict__ out) {
    int mbase = blockIdx.y * BM;
    int ntile = blockIdx.x;

    extern __shared__ char smem[];
    u32 sb = smem_u32(smem);
    int tid = threadIdx.x, wid = tid >> 5, lane = tid & 31;

    size_t slotBase = (size_t)EE * CAP + mbase;

    int pw = tid >> 5, psub = (tid >> 3) & 3, pc = tid & 7;
    u32 sOff[4];
    #pragma unroll
    for (int j = 0; j < 4; ++j) {
        int r = pw * 16 + j * 4 + psub;
        sOff[j] = ((u32)(r * 128 + pc * 16)) ^ ((u32)((r & 7) << 4));
    }
    const __half* aSrc = g_hh + (slotBase + (size_t)(pw * 16 + psub)) * HH + pc * 8;
    const __half* bSrc = g_wd + (size_t)(EE * DD + ntile * BN + pw * 16 + psub) * HH + pc * 8;

#define ISSUE(s) do { \
    u32 _st = sb + (u32)((s) % NSTAGE) * STG; \
    _Pragma("unroll") \
    for (int j = 0; j < 4; ++j) cpa16(_st + sOff[j], aSrc + j * 4 * HH + (s) * BK); \
    _Pragma("unroll") \
    for (int j = 0; j < 4; ++j) cpa16(_st + S_B + sOff[j], bSrc + j * 4 * HH + (s) * BK); \
} while (0)

    FRAG_SETUP();
    MAINLOOP(HH / BK);  // 32 chunks, full K
#undef ISSUE

    int rbase = wm * 32 + (lane >> 2), cquad = lane & 3;
    #pragma unroll
    for (int mt = 0; mt < 2; ++mt)
        #pragma unroll
        for (int nt = 0; nt < 8; ++nt) {
            int col = ntile * BN + wn * 64 + nt * 8 + cquad * 2;
            float* c = acc[mt][nt];
            #pragma unroll
            for (int half = 0; half < 2; ++half) {
                int r = rbase + mt * 16 + half * 8;
                *(float2*)(out + (size_t)(mbase + r) * DD + col) =
                    make_float2(c[half * 2], c[half * 2 + 1]);
            }
        }
}

// =====================================================================
// GEMM2 routed: full K; weighted red.v2 scatter on top of shared output
// =====================================================================
__global__ void __launch_bounds__(256, 2)
gemm2r_kernel(float* __restrict__ out) {
    int e = blockIdx.z;
    int ne = g_cnt[e];
    int mbase = blockIdx.y * BM;
    if (mbase >= ne) return;
    int ntile = blockIdx.x;

    extern __shared__ char smem[];
    u32 sb = smem_u32(smem);
    __shared__ int   s_tok[128];
    __shared__ float s_wt[128];
    int tid = threadIdx.x, wid = tid >> 5, lane = tid & 31;
    if (tid < 128) {
        int r = mbase + tid;
        if (r < ne) { s_tok[tid] = g_tok[e * CAP + r]; s_wt[tid] = g_wt[e * CAP + r]; }
        else        { s_tok[tid] = 0; s_wt[tid] = 0.f; }
    }
    __syncthreads();

    size_t slotBase = (size_t)e * CAP + mbase;

    int pw = tid >> 5, psub = (tid >> 3) & 3, pc = tid & 7;
    u32 sOff[4];
    #pragma unroll
    for (int j = 0; j < 4; ++j) {
        int r = pw * 16 + j * 4 + psub;
        sOff[j] = ((u32)(r * 128 + pc * 16)) ^ ((u32)((r & 7) << 4));
    }
    const __half* aSrc = g_hh + (slotBase + (size_t)(pw * 16 + psub)) * HH + pc * 8;
    const __half* bSrc = g_wd + (size_t)(e * DD + ntile * BN + pw * 16 + psub) * HH + pc * 8;

#define ISSUE(s) do { \
    u32 _st = sb + (u32)((s) % NSTAGE) * STG; \
    _Pragma("unroll") \
    for (int j = 0; j < 4; ++j) cpa16(_st + sOff[j], aSrc + j * 4 * HH + (s) * BK); \
    _Pragma("unroll") \
    for (int j = 0; j < 4; ++j) cpa16(_st + S_B + sOff[j], bSrc + j * 4 * HH + (s) * BK); \
} while (0)

    FRAG_SETUP();
    MAINLOOP(HH / BK);  // 32 chunks, full K
#undef ISSUE

    int nv = ne - mbase; if (nv > BM) nv = BM;
    int rbase = wm * 32 + (lane >> 2), cquad = lane & 3;
    #pragma unroll
    for (int mt = 0; mt < 2; ++mt)
        #pragma unroll
        for (int nt = 0; nt < 8; ++nt) {
            int col = ntile * BN + wn * 64 + nt * 8 + cquad * 2;
            float* c = acc[mt][nt];
            #pragma unroll
            for (int half = 0; half < 2; ++half) {
                int r = rbase + mt * 16 + half * 8;
                if (r < nv) {
                    int tok = s_tok[r]; float wt = s_wt[r];
                    red2(out + (size_t)tok * DD + col,
                         wt * c[half * 2], wt * c[half * 2 + 1]);
                }
            }
        }
}

// ---------------- launch ----------------
extern "C" void kernel_launch(void* const* d_in, const int* in_sizes, int n_in,
                              void* d_out, int out_size) {
    const float* x  = (const float*)d_in[0];
    const float* wr = (const float*)d_in[1];
    const float* Wg = (const float*)d_in[2];
    const float* Wu = (const float*)d_in[3];
    const float* Wd = (const float*)d_in[4];
    const float* sg = (const float*)d_in[5];
    const float* su = (const float*)d_in[6];
    const float* sd = (const float*)d_in[7];
    float* out = (float*)d_out;

    cudaFuncSetAttribute(gemm1_kernel,  cudaFuncAttributeMaxDynamicSharedMemorySize, SMEM_DYN);
    cudaFuncSetAttribute(gemm2s_kernel, cudaFuncAttributeMaxDynamicSharedMemorySize, SMEM_DYN);
    cudaFuncSetAttribute(gemm2r_kernel, cudaFuncAttributeMaxDynamicSharedMemorySize, SMEM_DYN);

    // gemm1 stays launch #4 (ncu slot)
    conv_x_router_kernel<<<T_TOK, 256>>>(x, wr);
    conv_wgu_kernel<<<NEXP * 4096 / 4, 256>>>(Wg, Wu, sg, su);
    conv_wd_kernel<<<NEXP * DD / 2, 512>>>(Wd, sd);

    dim3 g1(32, 32, NEXP);
    gemm1_kernel<<<g1, 256, SMEM_DYN>>>();

    dim3 g2s(8, 32);               // shared expert: STG base (must precede red)
    gemm2s_kernel<<<g2s, 256, SMEM_DYN>>>(out);

    dim3 g2r(8, 32, EE);           // routed experts: red.v2 on top
    gemm2r_kernel<<<g2r, 256, SMEM_DYN>>>(out);
}